// round 8
// baseline (speedup 1.0000x reference)
#include <cuda_runtime.h>
#include <cuda_bf16.h>
#include <cstdint>

#define CDIM    128
#define KTOT    1024
#define MV      128
#define NTL     128      // codes per staged tile
#define NTILES  8
#define HW      4096
#define NTHREADS 256

// dynamic SMEM byte offsets
#define SM_SE    0        // 1024 f  ||e||^2
#define SM_VN    4096     // 128 f   ||z||^2
#define SM_RK1   4608     // 128 i
#define SM_RK2   5120     // 128 i
#define SM_RNE   5632     // 128 i
#define SM_ZS    6144     // 16384 f exact z [c][v]
#define SM_ZH    71680    // 32KB bf16 A-tile image (hi)
#define SM_ZL    104448   // 32KB (lo)
#define SM_BH    137216   // 32KB bf16 B-tile image (hi)
#define SM_BL    169984   // 32KB (lo)
#define SM_TOTAL 202752

#define RESCUE_EPS 2e-3f

// device scratch (no allocations allowed)
__device__ float  g_enorm[KTOT];
__device__ int    g_used[KTOT];
__device__ double g_sq;
__device__ __align__(16) __nv_bfloat16 g_cbh[NTILES][NTL * CDIM];  // swizzled images
__device__ __align__(16) __nv_bfloat16 g_cbl[NTILES][NTL * CDIM];

__device__ __forceinline__ uint32_t s2u(const void* p) {
    uint32_t a;
    asm("{ .reg .u64 t; cvta.to.shared.u64 t, %1; cvt.u32.u64 %0, t; }" : "=r"(a) : "l"(p));
    return a;
}

// byte offset of (row r, k-col c) in a 128x128-bf16 tile image, 256B/row,
// 16B chunks XOR-swizzled so ldmatrix (8 rows, same chunk) is conflict-free
__device__ __forceinline__ int toff(int r, int c) {
    return r * 256 + (((c >> 3) ^ (r & 7)) << 4) + ((c & 7) << 1);
}

// top-2 update with (score, index) lexicographic order (first-index-wins)
__device__ __forceinline__ void upd2(float d, int kg, float& b1, int& k1,
                                     float& b2, int& k2) {
    if (d < b1 || (d == b1 && kg < k1)) { b2 = b1; k2 = k1; b1 = d; k1 = kg; }
    else if (d < b2 || (d == b2 && kg < k2)) { b2 = d; k2 = kg; }
}

// ---------------------------------------------------------------------------
// Kernel 1: prep — enorm, usage/accumulator reset, split codebook tile images
// ---------------------------------------------------------------------------
__global__ void vq_prep(const float* __restrict__ cb) {
    int k = blockIdx.x * 128 + threadIdx.x;     // 0..1023
    g_used[k] = 0;
    if (k == 0) g_sq = 0.0;
    const float* row = cb + (size_t)k * CDIM;
    int nt = k >> 7, r = k & 127;
    uint8_t* ih = (uint8_t*)g_cbh[nt];
    uint8_t* il = (uint8_t*)g_cbl[nt];
    float s = 0.f;
    #pragma unroll 4
    for (int c = 0; c < CDIM; ++c) {
        float x = row[c];
        s = __fmaf_rn(x, x, s);                 // exact ascending chain
        __nv_bfloat16 h = __float2bfloat16(x);
        __nv_bfloat16 l = __float2bfloat16(__fsub_rn(x, __bfloat162float(h)));
        int off = toff(r, c);
        *(__nv_bfloat16*)(ih + off) = h;
        *(__nv_bfloat16*)(il + off) = l;
    }
    g_enorm[k] = s;
}

// ---------------------------------------------------------------------------
// Kernel 2: main — mma.sync bf16 3-split distance GEMM + top2 + exact rescue
// ---------------------------------------------------------------------------
__global__ void __launch_bounds__(NTHREADS, 1) vq_mma(
    const float* __restrict__ z, const float* __restrict__ cb,
    float* __restrict__ out)
{
    extern __shared__ char smem[];
    const uint32_t sb = s2u(smem);
    const int tid  = threadIdx.x;
    const int w    = tid >> 5;
    const int lane = tid & 31;
    const int g    = lane >> 2;
    const int tg   = lane & 3;
    const int m0   = w << 4;                    // warp's 16 M-rows

    float* se  = (float*)(smem + SM_SE);
    float* vna = (float*)(smem + SM_VN);
    int*   rk1 = (int*)(smem + SM_RK1);
    int*   rk2 = (int*)(smem + SM_RK2);
    int*   rne = (int*)(smem + SM_RNE);
    float* zs  = (float*)(smem + SM_ZS);

    #pragma unroll
    for (int i = tid; i < KTOT; i += NTHREADS) se[i] = g_enorm[i];

    // ---- stage z: exact fp32 [c][v] + swizzled bf16 hi/lo A-tiles ----
    const int n0 = blockIdx.x * MV;
    const int b  = n0 >> 12;
    const int p0 = n0 & (HW - 1);
    const float* zb = z + (size_t)b * CDIM * HW + p0;
    uint8_t* zh = (uint8_t*)smem + SM_ZH;
    uint8_t* zl = (uint8_t*)smem + SM_ZL;
    #pragma unroll 4
    for (int idx = tid; idx < CDIM * MV; idx += NTHREADS) {
        int c = idx >> 7, v = idx & 127;
        float x = zb[(size_t)c * HW + v];
        zs[c * 128 + v] = x;
        __nv_bfloat16 h = __float2bfloat16(x);
        __nv_bfloat16 l = __float2bfloat16(__fsub_rn(x, __bfloat162float(h)));
        int off = toff(v, c);                   // A-tile: row = vector, col = c
        *(__nv_bfloat16*)(zh + off) = h;
        *(__nv_bfloat16*)(zl + off) = l;
    }
    __syncthreads();

    // ||z||^2 per vector (vn cancels in argmin; order-insensitive)
    if (tid < MV) {
        float s = 0.f;
        #pragma unroll 8
        for (int c = 0; c < CDIM; ++c) {
            float x = zs[c * 128 + tid];
            s = __fmaf_rn(x, x, s);
        }
        vna[tid] = s;
    }
    __syncthreads();

    const float vnL = vna[m0 + g];
    const float vnH = vna[m0 + g + 8];

    float b1L = 3.4e38f, b2L = 3.4e38f, b1H = 3.4e38f, b2H = 3.4e38f;
    int   k1L = 0, k2L = 0, k1H = 0, k2H = 0;

    for (int nt = 0; nt < NTILES; ++nt) {
        // ---- stage B tile images (flat coalesced 64KB copy) ----
        {
            const uint4* sh = (const uint4*)g_cbh[nt];
            const uint4* sl = (const uint4*)g_cbl[nt];
            uint4* dh = (uint4*)(smem + SM_BH);
            uint4* dl = (uint4*)(smem + SM_BL);
            #pragma unroll 4
            for (int i = tid; i < 2048; i += NTHREADS) { dh[i] = sh[i]; dl[i] = sl[i]; }
        }
        __syncthreads();

        #pragma unroll 1
        for (int g32 = 0; g32 < 4; ++g32) {     // 32 codes per group
            float acc[4][4];
            #pragma unroll
            for (int j = 0; j < 4; ++j)
                #pragma unroll
                for (int q = 0; q < 4; ++q) acc[j][q] = 0.f;

            #pragma unroll
            for (int split = 0; split < 3; ++split) {
                uint32_t Ab = sb + (split == 2 ? SM_ZL : SM_ZH);
                uint32_t Bb = sb + (split == 1 ? SM_BL : SM_BH);
                #pragma unroll
                for (int kk = 0; kk < 8; ++kk) {
                    // A fragment: m16 x k16 via ldmatrix.x4
                    int mat = lane >> 3;
                    int ar  = m0 + (lane & 7) + ((mat & 1) << 3);
                    int ac  = (kk << 1) + (mat >> 1);          // 16B chunk idx
                    uint32_t aaddr = Ab + ar * 256 + (((ac ^ (ar & 7))) << 4);
                    uint32_t a0, a1, a2, a3;
                    asm volatile(
                        "ldmatrix.sync.aligned.m8n8.x4.shared.b16 {%0,%1,%2,%3}, [%4];"
                        : "=r"(a0), "=r"(a1), "=r"(a2), "=r"(a3) : "r"(aaddr));
                    #pragma unroll
                    for (int j = 0; j < 4; ++j) {
                        // B fragment: k16 x n8 (codebook rows are n, k contiguous)
                        int br = (g32 << 5) + (j << 3) + (lane & 7);
                        int bc = (kk << 1) + ((lane >> 3) & 1);
                        uint32_t baddr = Bb + br * 256 + (((bc ^ (br & 7))) << 4);
                        uint32_t bb0, bb1;
                        asm volatile(
                            "ldmatrix.sync.aligned.m8n8.x2.shared.b16 {%0,%1}, [%2];"
                            : "=r"(bb0), "=r"(bb1) : "r"(baddr));
                        asm volatile(
                            "mma.sync.aligned.m16n8k16.row.col.f32.bf16.bf16.f32 "
                            "{%0,%1,%2,%3}, {%4,%5,%6,%7}, {%8,%9}, {%0,%1,%2,%3};"
                            : "+f"(acc[j][0]), "+f"(acc[j][1]),
                              "+f"(acc[j][2]), "+f"(acc[j][3])
                            : "r"(a0), "r"(a1), "r"(a2), "r"(a3),
                              "r"(bb0), "r"(bb1));
                    }
                }
            }

            // ---- scores + running top-2 ----
            int kgb = nt * NTL + (g32 << 5);
            #pragma unroll
            for (int j = 0; j < 4; ++j) {
                int c0 = kgb + (j << 3) + (tg << 1);
                float s0 = se[c0], s1 = se[c0 + 1];
                float d;
                d = __fsub_rn(__fadd_rn(vnL, s0), __fmul_rn(2.f, acc[j][0]));
                upd2(d, c0,     b1L, k1L, b2L, k2L);
                d = __fsub_rn(__fadd_rn(vnL, s1), __fmul_rn(2.f, acc[j][1]));
                upd2(d, c0 + 1, b1L, k1L, b2L, k2L);
                d = __fsub_rn(__fadd_rn(vnH, s0), __fmul_rn(2.f, acc[j][2]));
                upd2(d, c0,     b1H, k1H, b2H, k2H);
                d = __fsub_rn(__fadd_rn(vnH, s1), __fmul_rn(2.f, acc[j][3]));
                upd2(d, c0 + 1, b1H, k1H, b2H, k2H);
            }
        }
        __syncthreads();    // all warps done reading B before restage
    }

    // ---- merge top-2 across the 4 lanes of each quad ----
    #pragma unroll
    for (int delta = 1; delta <= 2; delta <<= 1) {
        float o1 = __shfl_xor_sync(0xffffffffu, b1L, delta);
        int   p1 = __shfl_xor_sync(0xffffffffu, k1L, delta);
        float o2 = __shfl_xor_sync(0xffffffffu, b2L, delta);
        int   p2 = __shfl_xor_sync(0xffffffffu, k2L, delta);
        upd2(o1, p1, b1L, k1L, b2L, k2L);
        upd2(o2, p2, b1L, k1L, b2L, k2L);
        o1 = __shfl_xor_sync(0xffffffffu, b1H, delta);
        p1 = __shfl_xor_sync(0xffffffffu, k1H, delta);
        o2 = __shfl_xor_sync(0xffffffffu, b2H, delta);
        p2 = __shfl_xor_sync(0xffffffffu, k2H, delta);
        upd2(o1, p1, b1H, k1H, b2H, k2H);
        upd2(o2, p2, b1H, k1H, b2H, k2H);
    }
    if (tg == 0) {
        int rL = m0 + g, rH = m0 + g + 8;
        rk1[rL] = k1L; rk2[rL] = k2L; rne[rL] = (__fsub_rn(b2L, b1L) <= RESCUE_EPS);
        rk1[rH] = k1H; rk2[rH] = k2H; rne[rH] = (__fsub_rn(b2H, b1H) <= RESCUE_EPS);
    }
    __syncthreads();

    // ---- exact rescue + output epilogue (thread v = row) ----
    float errsum = 0.f;
    if (tid < MV) {
        int v = tid;
        int kb = rk1[v];
        if (rne[v]) {
            int ka = kb, kc = rk2[v];
            float vn = vna[v];
            float d1, d2;
            {
                const float* row = cb + (size_t)ka * CDIM;
                float dot = 0.f;
                #pragma unroll 8
                for (int c = 0; c < CDIM; ++c)
                    dot = __fmaf_rn(zs[c * 128 + v], row[c], dot);
                d1 = __fsub_rn(__fadd_rn(vn, se[ka]), __fmul_rn(2.0f, dot));
            }
            {
                const float* row = cb + (size_t)kc * CDIM;
                float dot = 0.f;
                #pragma unroll 8
                for (int c = 0; c < CDIM; ++c)
                    dot = __fmaf_rn(zs[c * 128 + v], row[c], dot);
                d2 = __fsub_rn(__fadd_rn(vn, se[kc]), __fmul_rn(2.0f, dot));
            }
            kb = (d2 < d1 || (d2 == d1 && kc < ka)) ? kc : ka;
        }
        g_used[kb] = 1;

        // z_q_st = fl(z + fl(z_q - z)) in (B,C,H,W); MSE partial
        const float4* crow = (const float4*)(cb + (size_t)kb * CDIM);
        float* ob = out + (size_t)b * CDIM * HW + p0 + v;
        #pragma unroll 4
        for (int c4 = 0; c4 < 32; ++c4) {
            float4 e4 = crow[c4];
            float ee[4] = {e4.x, e4.y, e4.z, e4.w};
            #pragma unroll
            for (int jj = 0; jj < 4; ++jj) {
                int c = c4 * 4 + jj;
                float zv = zs[c * 128 + v];
                float t  = __fsub_rn(ee[jj], zv);
                ob[(size_t)c * HW] = __fadd_rn(zv, t);
                errsum = __fmaf_rn(t, t, errsum);
            }
        }
    }

    // ---- block reduce squared error -> double atomic ----
    __syncthreads();
    float* red = (float*)(smem + SM_SE);       // se no longer needed
    if (tid < MV) red[tid] = errsum;
    __syncthreads();
    if (tid < 64) red[tid] = __fadd_rn(red[tid], red[tid + 64]);
    __syncthreads();
    if (tid < 32) {
        float s = __fadd_rn(red[tid], red[tid + 32]);
        #pragma unroll
        for (int off = 16; off; off >>= 1)
            s = __fadd_rn(s, __shfl_down_sync(0xffffffffu, s, off));
        if (tid == 0) atomicAdd(&g_sq, (double)s);
    }
}

// ---------------------------------------------------------------------------
// Kernel 3: finalize — vq_loss + usage scalars
// ---------------------------------------------------------------------------
__global__ void vq_fin(float* __restrict__ out, int npix) {
    __shared__ int cnt[32];
    int tid = threadIdx.x;             // 1024 threads
    int u = g_used[tid] ? 1 : 0;
    #pragma unroll
    for (int off = 16; off; off >>= 1) u += __shfl_down_sync(0xffffffffu, u, off);
    if ((tid & 31) == 0) cnt[tid >> 5] = u;
    __syncthreads();
    if (tid == 0) {
        int total = 0;
        #pragma unroll
        for (int i = 0; i < 32; ++i) total += cnt[i];
        float m  = (float)(g_sq / (double)npix);
        float vq = __fadd_rn(m, __fmul_rn(0.25f, m));
        out[npix]     = vq;
        out[npix + 1] = (float)total * (1.0f / 1024.0f);
    }
}

// ---------------------------------------------------------------------------
extern "C" void kernel_launch(void* const* d_in, const int* in_sizes, int n_in,
                              void* d_out, int out_size) {
    const float* z  = (const float*)d_in[0];
    const float* cb = (const float*)d_in[1];
    float* out = (float*)d_out;
    int npix = out_size - 2;                    // 8388608
    int nvec = npix / CDIM;                     // 65536
    int blocks = nvec / MV;                     // 512

    cudaFuncSetAttribute(vq_mma, cudaFuncAttributeMaxDynamicSharedMemorySize, SM_TOTAL);

    vq_prep<<<KTOT / 128, 128>>>(cb);
    vq_mma<<<blocks, NTHREADS, SM_TOTAL>>>(z, cb, out);
    vq_fin<<<1, KTOT>>>(out, npix);
}

// round 12
// speedup vs baseline: 2.2802x; 2.2802x over previous
#include <cuda_runtime.h>
#include <cuda_bf16.h>
#include <cstdint>

#define CDIM    128
#define KTOT    1024
#define MV      128
#define NTL     128
#define NTILES  8
#define HW      4096
#define NTHREADS 256

// dynamic SMEM byte offsets
#define SM_SE    0        // 1024 f  exact ||e||^2
#define SM_SE1   4096     // 1024 f  ||e||^2 + 1.0 (key domain)
#define SM_VN    8192     // 128 f
#define SM_RK    8704     // 128*4 i  candidate indices
#define SM_RNE   10752    // 128 i    rescue flags
#define SM_ZS    11264    // 64KB exact z fp32 [c][v]
#define SM_ZH    76800    // 32KB bf16 A-tile image
#define SM_BH    109568   // 32KB bf16 B-tile image
#define SM_TOTAL 142336   // = SM_BH + 32768 (R11 bug: was 141312, B-tile overran)

#define RESCUE_EPS 2e-3f

// device scratch (no allocations allowed)
__device__ float  g_enorm[KTOT];
__device__ int    g_used[KTOT];
__device__ double g_sq;
__device__ __align__(16) __nv_bfloat16 g_cbh[NTILES][NTL * CDIM];  // swizzled images

__device__ __forceinline__ uint32_t s2u(const void* p) {
    uint32_t a;
    asm("{ .reg .u64 t; cvta.to.shared.u64 t, %1; cvt.u32.u64 %0, t; }" : "=r"(a) : "l"(p));
    return a;
}

// byte offset of (row r, k-col c) in a 128x128-bf16 tile image, 256B/row,
// 16B chunks XOR-swizzled so ldmatrix (8 rows, same chunk) is conflict-free
__device__ __forceinline__ int toff(int r, int c) {
    return r * 256 + (((c >> 3) ^ (r & 7)) << 4) + ((c & 7) << 1);
}

// monotone key: positive-float score bits (top 22) | code index (low 10)
__device__ __forceinline__ uint32_t mkkey(float r, int code) {
    return (__float_as_uint(r) & 0xFFFFFC00u) | (uint32_t)code;
}
// branch-free sorted-4 insertion (b1 <= b2 <= b3 <= b4)
__device__ __forceinline__ void ins4(uint32_t k, uint32_t& b1, uint32_t& b2,
                                     uint32_t& b3, uint32_t& b4) {
    uint32_t t;
    t = umax(k, b1); b1 = umin(k, b1); k = t;
    t = umax(k, b2); b2 = umin(k, b2); k = t;
    t = umax(k, b3); b3 = umin(k, b3); k = t;
    b4 = umin(k, b4);
}

// ---------------------------------------------------------------------------
// Kernel 1: prep — enorm (warp-reduced), resets, bf16 codebook tile image
// ---------------------------------------------------------------------------
__global__ void vq_prep(const float* __restrict__ cb) {
    int w    = threadIdx.x >> 5;
    int lane = threadIdx.x & 31;
    int k    = blockIdx.x * 4 + w;              // 0..1023
    int c    = lane << 2;

    float4 v = ((const float4*)(cb + (size_t)k * CDIM))[lane];
    float s = __fmaf_rn(v.x, v.x, 0.f);
    s = __fmaf_rn(v.y, v.y, s);
    s = __fmaf_rn(v.z, v.z, s);
    s = __fmaf_rn(v.w, v.w, s);
    #pragma unroll
    for (int off = 16; off; off >>= 1)
        s = __fadd_rn(s, __shfl_down_sync(0xffffffffu, s, off));

    int nt = k >> 7, r = k & 127;
    uint8_t* img = (uint8_t*)g_cbh[nt] + toff(r, c);
    __nv_bfloat162 p0, p1;
    p0.x = __float2bfloat16(v.x); p0.y = __float2bfloat16(v.y);
    p1.x = __float2bfloat16(v.z); p1.y = __float2bfloat16(v.w);
    *(__nv_bfloat162*)(img)     = p0;
    *(__nv_bfloat162*)(img + 4) = p1;

    if (lane == 0) { g_enorm[k] = s; g_used[k] = 0; if (k == 0) g_sq = 0.0; }
}

// ---------------------------------------------------------------------------
// Kernel 2: main — bf16 mma.sync GEMM + keyed top-4 + exact 4-way rescue
// ---------------------------------------------------------------------------
__global__ void __launch_bounds__(NTHREADS, 1) vq_mma(
    const float* __restrict__ z, const float* __restrict__ cb,
    float* __restrict__ out)
{
    extern __shared__ char smem[];
    const uint32_t sb = s2u(smem);
    const int tid  = threadIdx.x;
    const int w    = tid >> 5;
    const int lane = tid & 31;
    const int g    = lane >> 2;
    const int tg   = lane & 3;
    const int m0   = w << 4;

    float* se  = (float*)(smem + SM_SE);
    float* se1 = (float*)(smem + SM_SE1);
    float* vna = (float*)(smem + SM_VN);
    int*   rk  = (int*)(smem + SM_RK);
    int*   rne = (int*)(smem + SM_RNE);
    float* zs  = (float*)(smem + SM_ZS);

    #pragma unroll
    for (int i = tid; i < KTOT; i += NTHREADS) {
        float e = g_enorm[i];
        se[i]  = e;
        se1[i] = __fadd_rn(e, 1.0f);
    }

    // ---- stage z: exact fp32 [c][v] + swizzled bf16 A-tile ----
    const int n0 = blockIdx.x * MV;
    const int b  = n0 >> 12;
    const int p0 = n0 & (HW - 1);
    const float* zb = z + (size_t)b * CDIM * HW + p0;
    uint8_t* zh = (uint8_t*)smem + SM_ZH;
    #pragma unroll 4
    for (int idx = tid; idx < CDIM * MV; idx += NTHREADS) {
        int c = idx >> 7, v = idx & 127;
        float x = zb[(size_t)c * HW + v];
        zs[c * 128 + v] = x;
        *(__nv_bfloat16*)(zh + toff(v, c)) = __float2bfloat16(x);
    }
    __syncthreads();

    // ||z||^2 per vector (exact ascending chain; used by rescue)
    if (tid < MV) {
        float s = 0.f;
        #pragma unroll 8
        for (int c = 0; c < CDIM; ++c) {
            float x = zs[c * 128 + tid];
            s = __fmaf_rn(x, x, s);
        }
        vna[tid] = s;
    }
    __syncthreads();

    // ---- load A fragments ONCE (z static): 8 x ldmatrix.x4 ----
    uint32_t afr[8][4];
    {
        int mat = lane >> 3;
        int ar  = m0 + (lane & 7) + ((mat & 1) << 3);
        uint32_t arow = sb + SM_ZH + ar * 256;
        #pragma unroll
        for (int kk = 0; kk < 8; ++kk) {
            int ac = (kk << 1) + (mat >> 1);
            uint32_t aaddr = arow + (((ac ^ (ar & 7))) << 4);
            asm volatile(
                "ldmatrix.sync.aligned.m8n8.x4.shared.b16 {%0,%1,%2,%3}, [%4];"
                : "=r"(afr[kk][0]), "=r"(afr[kk][1]),
                  "=r"(afr[kk][2]), "=r"(afr[kk][3]) : "r"(aaddr));
        }
    }

    // keyed top-4, rows L (m0+g) and H (m0+g+8)
    uint32_t L1 = 0xFFFFFFFFu, L2 = 0xFFFFFFFFu, L3 = 0xFFFFFFFFu, L4 = 0xFFFFFFFFu;
    uint32_t H1 = 0xFFFFFFFFu, H2 = 0xFFFFFFFFu, H3 = 0xFFFFFFFFu, H4 = 0xFFFFFFFFu;

    const int brow_lane = lane & 7;
    const int bcol_lane = (lane >> 3) & 1;

    for (int nt = 0; nt < NTILES; ++nt) {
        // ---- stage B tile image (flat 32KB coalesced copy) ----
        {
            const uint4* sh = (const uint4*)g_cbh[nt];
            uint4* dh = (uint4*)(smem + SM_BH);
            #pragma unroll
            for (int i = tid; i < 2048; i += NTHREADS) dh[i] = sh[i];
        }
        __syncthreads();

        #pragma unroll 1
        for (int g32 = 0; g32 < 4; ++g32) {     // 32 codes per group
            float acc[4][4];
            #pragma unroll
            for (int j = 0; j < 4; ++j)
                #pragma unroll
                for (int q = 0; q < 4; ++q) acc[j][q] = 0.f;

            #pragma unroll
            for (int h = 0; h < 2; ++h) {
                uint32_t bf[4][4][2];
                #pragma unroll
                for (int kk2 = 0; kk2 < 4; ++kk2) {
                    int bc = ((h << 2) + kk2) * 2 + bcol_lane;
                    #pragma unroll
                    for (int j = 0; j < 4; ++j) {
                        int br = (g32 << 5) + (j << 3) + brow_lane;
                        uint32_t baddr = sb + SM_BH + br * 256 + (((bc ^ (br & 7))) << 4);
                        asm volatile(
                            "ldmatrix.sync.aligned.m8n8.x2.shared.b16 {%0,%1}, [%2];"
                            : "=r"(bf[kk2][j][0]), "=r"(bf[kk2][j][1]) : "r"(baddr));
                    }
                }
                #pragma unroll
                for (int kk2 = 0; kk2 < 4; ++kk2) {
                    int kk = (h << 2) + kk2;
                    #pragma unroll
                    for (int j = 0; j < 4; ++j) {
                        asm volatile(
                            "mma.sync.aligned.m16n8k16.row.col.f32.bf16.bf16.f32 "
                            "{%0,%1,%2,%3}, {%4,%5,%6,%7}, {%8,%9}, {%0,%1,%2,%3};"
                            : "+f"(acc[j][0]), "+f"(acc[j][1]),
                              "+f"(acc[j][2]), "+f"(acc[j][3])
                            : "r"(afr[kk][0]), "r"(afr[kk][1]),
                              "r"(afr[kk][2]), "r"(afr[kk][3]),
                              "r"(bf[kk2][j][0]), "r"(bf[kk2][j][1]));
                    }
                }
            }

            // ---- keyed approx ranking: r = (se+1) - 2*dot ----
            int kgb = nt * NTL + (g32 << 5);
            #pragma unroll
            for (int j = 0; j < 4; ++j) {
                int c0 = kgb + (j << 3) + (tg << 1);
                float s0 = se1[c0], s1 = se1[c0 + 1];
                ins4(mkkey(__fmaf_rn(-2.f, acc[j][0], s0), c0),     L1, L2, L3, L4);
                ins4(mkkey(__fmaf_rn(-2.f, acc[j][1], s1), c0 + 1), L1, L2, L3, L4);
                ins4(mkkey(__fmaf_rn(-2.f, acc[j][2], s0), c0),     H1, H2, H3, H4);
                ins4(mkkey(__fmaf_rn(-2.f, acc[j][3], s1), c0 + 1), H1, H2, H3, H4);
            }
        }
        __syncthreads();    // all warps done reading BH before restage
    }

    // ---- merge top-4 across the 4 lanes of each quad ----
    #pragma unroll
    for (int d = 1; d <= 2; d <<= 1) {
        uint32_t o1 = __shfl_xor_sync(0xffffffffu, L1, d);
        uint32_t o2 = __shfl_xor_sync(0xffffffffu, L2, d);
        uint32_t o3 = __shfl_xor_sync(0xffffffffu, L3, d);
        uint32_t o4 = __shfl_xor_sync(0xffffffffu, L4, d);
        ins4(o1, L1, L2, L3, L4); ins4(o2, L1, L2, L3, L4);
        ins4(o3, L1, L2, L3, L4); ins4(o4, L1, L2, L3, L4);
        o1 = __shfl_xor_sync(0xffffffffu, H1, d);
        o2 = __shfl_xor_sync(0xffffffffu, H2, d);
        o3 = __shfl_xor_sync(0xffffffffu, H3, d);
        o4 = __shfl_xor_sync(0xffffffffu, H4, d);
        ins4(o1, H1, H2, H3, H4); ins4(o2, H1, H2, H3, H4);
        ins4(o3, H1, H2, H3, H4); ins4(o4, H1, H2, H3, H4);
    }
    if (tg == 0) {
        int rL = m0 + g, rH = m0 + g + 8;
        rk[rL * 4 + 0] = L1 & 1023; rk[rL * 4 + 1] = L2 & 1023;
        rk[rL * 4 + 2] = L3 & 1023; rk[rL * 4 + 3] = L4 & 1023;
        rk[rH * 4 + 0] = H1 & 1023; rk[rH * 4 + 1] = H2 & 1023;
        rk[rH * 4 + 2] = H3 & 1023; rk[rH * 4 + 3] = H4 & 1023;
        float sL1 = __uint_as_float(L1 & 0xFFFFFC00u);
        float sL2 = __uint_as_float(L2 & 0xFFFFFC00u);
        float sH1 = __uint_as_float(H1 & 0xFFFFFC00u);
        float sH2 = __uint_as_float(H2 & 0xFFFFFC00u);
        rne[rL] = (__fsub_rn(sL2, sL1) <= RESCUE_EPS);
        rne[rH] = (__fsub_rn(sH2, sH1) <= RESCUE_EPS);
    }
    __syncthreads();

    // ---- exact 4-way rescue (reference fp32 chain) + output epilogue ----
    float errsum = 0.f;
    if (tid < MV) {
        int v = tid;
        int kb = rk[v * 4];
        if (rne[v]) {
            int k0 = rk[v * 4], k1 = rk[v * 4 + 1],
                k2 = rk[v * 4 + 2], k3 = rk[v * 4 + 3];
            const float* r0 = cb + (size_t)k0 * CDIM;
            const float* r1 = cb + (size_t)k1 * CDIM;
            const float* r2 = cb + (size_t)k2 * CDIM;
            const float* r3 = cb + (size_t)k3 * CDIM;
            float d0 = 0.f, d1 = 0.f, d2 = 0.f, d3 = 0.f;
            #pragma unroll 8
            for (int c = 0; c < CDIM; ++c) {
                float zv = zs[c * 128 + v];
                d0 = __fmaf_rn(zv, r0[c], d0);
                d1 = __fmaf_rn(zv, r1[c], d1);
                d2 = __fmaf_rn(zv, r2[c], d2);
                d3 = __fmaf_rn(zv, r3[c], d3);
            }
            float vn = vna[v];
            float e0 = __fsub_rn(__fadd_rn(vn, se[k0]), __fmul_rn(2.0f, d0));
            float e1 = __fsub_rn(__fadd_rn(vn, se[k1]), __fmul_rn(2.0f, d1));
            float e2 = __fsub_rn(__fadd_rn(vn, se[k2]), __fmul_rn(2.0f, d2));
            float e3 = __fsub_rn(__fadd_rn(vn, se[k3]), __fmul_rn(2.0f, d3));
            float bd = e0; kb = k0;
            if (e1 < bd || (e1 == bd && k1 < kb)) { bd = e1; kb = k1; }
            if (e2 < bd || (e2 == bd && k2 < kb)) { bd = e2; kb = k2; }
            if (e3 < bd || (e3 == bd && k3 < kb)) { bd = e3; kb = k3; }
        }
        g_used[kb] = 1;

        // z_q_st = fl(z + fl(z_q - z)) in (B,C,H,W); MSE partial
        const float4* crow = (const float4*)(cb + (size_t)kb * CDIM);
        float* ob = out + (size_t)b * CDIM * HW + p0 + v;
        #pragma unroll 4
        for (int c4 = 0; c4 < 32; ++c4) {
            float4 e4 = crow[c4];
            float ee[4] = {e4.x, e4.y, e4.z, e4.w};
            #pragma unroll
            for (int jj = 0; jj < 4; ++jj) {
                int c = c4 * 4 + jj;
                float zv = zs[c * 128 + v];
                float t  = __fsub_rn(ee[jj], zv);
                ob[(size_t)c * HW] = __fadd_rn(zv, t);
                errsum = __fmaf_rn(t, t, errsum);
            }
        }
    }

    // ---- block reduce squared error -> double atomic ----
    __syncthreads();
    float* red = (float*)(smem + SM_SE);
    if (tid < MV) red[tid] = errsum;
    __syncthreads();
    if (tid < 64) red[tid] = __fadd_rn(red[tid], red[tid + 64]);
    __syncthreads();
    if (tid < 32) {
        float s = __fadd_rn(red[tid], red[tid + 32]);
        #pragma unroll
        for (int off = 16; off; off >>= 1)
            s = __fadd_rn(s, __shfl_down_sync(0xffffffffu, s, off));
        if (tid == 0) atomicAdd(&g_sq, (double)s);
    }
}

// ---------------------------------------------------------------------------
// Kernel 3: finalize — vq_loss + usage scalars
// ---------------------------------------------------------------------------
__global__ void vq_fin(float* __restrict__ out, int npix) {
    __shared__ int cnt[32];
    int tid = threadIdx.x;             // 1024 threads
    int u = g_used[tid] ? 1 : 0;
    #pragma unroll
    for (int off = 16; off; off >>= 1) u += __shfl_down_sync(0xffffffffu, u, off);
    if ((tid & 31) == 0) cnt[tid >> 5] = u;
    __syncthreads();
    if (tid == 0) {
        int total = 0;
        #pragma unroll
        for (int i = 0; i < 32; ++i) total += cnt[i];
        float m  = (float)(g_sq / (double)npix);
        float vq = __fadd_rn(m, __fmul_rn(0.25f, m));
        out[npix]     = vq;
        out[npix + 1] = (float)total * (1.0f / 1024.0f);
    }
}

// ---------------------------------------------------------------------------
extern "C" void kernel_launch(void* const* d_in, const int* in_sizes, int n_in,
                              void* d_out, int out_size) {
    const float* z  = (const float*)d_in[0];
    const float* cb = (const float*)d_in[1];
    float* out = (float*)d_out;
    int npix = out_size - 2;                    // 8388608
    int nvec = npix / CDIM;                     // 65536
    int blocks = nvec / MV;                     // 512

    cudaFuncSetAttribute(vq_mma, cudaFuncAttributeMaxDynamicSharedMemorySize, SM_TOTAL);

    vq_prep<<<KTOT / 4, 128>>>(cb);
    vq_mma<<<blocks, NTHREADS, SM_TOTAL>>>(z, cb, out);
    vq_fin<<<1, KTOT>>>(out, npix);
}

// round 13
// speedup vs baseline: 4.0405x; 1.7720x over previous
#include <cuda_runtime.h>
#include <cuda_bf16.h>
#include <cstdint>

#define CDIM    128
#define KTOT    1024
#define MV      128
#define NTL     128
#define NTILES  8
#define HW      4096
#define NTHREADS 256

// dynamic SMEM byte offsets (75KB total -> 2 CTAs/SM)
#define SM_SE    0        // 1024 f  exact ||e||^2
#define SM_SE1   4096     // 1024 f  ||e||^2 + 1.0 (key domain)
#define SM_VN    8192     // 128 f
#define SM_RK    8704     // 128*4 i  candidate indices
#define SM_RNE   10752    // 128 i    rescue flags
#define SM_ZH    11264    // 32KB bf16 A-tile image
#define SM_BH    44032    // 32KB bf16 B-tile image
#define SM_TOTAL 76800

#define RESCUE_EPS 2e-3f

// device scratch (no allocations allowed)
__device__ float  g_enorm[KTOT];
__device__ int    g_used[KTOT];
__device__ double g_sq;
__device__ __align__(16) __nv_bfloat16 g_cbh[NTILES][NTL * CDIM];  // swizzled images

__device__ __forceinline__ uint32_t s2u(const void* p) {
    uint32_t a;
    asm("{ .reg .u64 t; cvta.to.shared.u64 t, %1; cvt.u32.u64 %0, t; }" : "=r"(a) : "l"(p));
    return a;
}

// byte offset of (row r, k-col c) in a 128x128-bf16 tile image, 256B/row,
// 16B chunks XOR-swizzled so ldmatrix (8 rows, same chunk) is conflict-free
__device__ __forceinline__ int toff(int r, int c) {
    return r * 256 + (((c >> 3) ^ (r & 7)) << 4) + ((c & 7) << 1);
}

// monotone key: positive-float score bits (top 22) | code index (low 10)
__device__ __forceinline__ uint32_t mkkey(float r, int code) {
    return (__float_as_uint(r) & 0xFFFFFC00u) | (uint32_t)code;
}
// branch-free sorted-4 insertion (b1 <= b2 <= b3 <= b4)
__device__ __forceinline__ void ins4(uint32_t k, uint32_t& b1, uint32_t& b2,
                                     uint32_t& b3, uint32_t& b4) {
    uint32_t t;
    t = umax(k, b1); b1 = umin(k, b1); k = t;
    t = umax(k, b2); b2 = umin(k, b2); k = t;
    t = umax(k, b3); b3 = umin(k, b3); k = t;
    b4 = umin(k, b4);
}

// ---------------------------------------------------------------------------
// Kernel 0: no-op (shifts ncu's -s window so vq_mma can be profiled)
// ---------------------------------------------------------------------------
__global__ void vq_nop() {}

// ---------------------------------------------------------------------------
// Kernel 1: prep — enorm (warp-reduced), resets, bf16 codebook tile image
// ---------------------------------------------------------------------------
__global__ void vq_prep(const float* __restrict__ cb) {
    int w    = threadIdx.x >> 5;
    int lane = threadIdx.x & 31;
    int k    = blockIdx.x * 4 + w;              // 0..1023
    int c    = lane << 2;

    float4 v = ((const float4*)(cb + (size_t)k * CDIM))[lane];
    float s = __fmaf_rn(v.x, v.x, 0.f);
    s = __fmaf_rn(v.y, v.y, s);
    s = __fmaf_rn(v.z, v.z, s);
    s = __fmaf_rn(v.w, v.w, s);
    #pragma unroll
    for (int off = 16; off; off >>= 1)
        s = __fadd_rn(s, __shfl_down_sync(0xffffffffu, s, off));

    int nt = k >> 7, r = k & 127;
    uint8_t* img = (uint8_t*)g_cbh[nt] + toff(r, c);
    __nv_bfloat162 p0, p1;
    p0.x = __float2bfloat16(v.x); p0.y = __float2bfloat16(v.y);
    p1.x = __float2bfloat16(v.z); p1.y = __float2bfloat16(v.w);
    *(__nv_bfloat162*)(img)     = p0;
    *(__nv_bfloat162*)(img + 4) = p1;

    if (lane == 0) { g_enorm[k] = s; g_used[k] = 0; if (k == 0) g_sq = 0.0; }
}

// ---------------------------------------------------------------------------
// Kernel 2: main — bf16 mma.sync GEMM + keyed top-4 + exact 4-way rescue
// ---------------------------------------------------------------------------
__global__ void __launch_bounds__(NTHREADS, 2) vq_mma(
    const float* __restrict__ z, const float* __restrict__ cb,
    float* __restrict__ out)
{
    extern __shared__ char smem[];
    const uint32_t sb = s2u(smem);
    const int tid  = threadIdx.x;
    const int w    = tid >> 5;
    const int lane = tid & 31;
    const int g    = lane >> 2;
    const int tg   = lane & 3;
    const int m0   = w << 4;

    float* se  = (float*)(smem + SM_SE);
    float* se1 = (float*)(smem + SM_SE1);
    float* vna = (float*)(smem + SM_VN);
    int*   rk  = (int*)(smem + SM_RK);
    int*   rne = (int*)(smem + SM_RNE);

    #pragma unroll
    for (int i = tid; i < KTOT; i += NTHREADS) {
        float e = g_enorm[i];
        se[i]  = e;
        se1[i] = __fadd_rn(e, 1.0f);
    }

    // ---- stage z: swizzled bf16 A-tile (exact z stays in GMEM, L2-hot) ----
    const int n0 = blockIdx.x * MV;
    const int b  = n0 >> 12;
    const int p0 = n0 & (HW - 1);
    const float* zb = z + (size_t)b * CDIM * HW + p0;
    uint8_t* zh = (uint8_t*)smem + SM_ZH;
    #pragma unroll 4
    for (int idx = tid; idx < CDIM * MV; idx += NTHREADS) {
        int c = idx >> 7, v = idx & 127;
        float x = zb[(size_t)c * HW + v];
        *(__nv_bfloat16*)(zh + toff(v, c)) = __float2bfloat16(x);
    }

    // ||z||^2 per vector (exact ascending chain; coalesced GMEM reads)
    if (tid < MV) {
        float s = 0.f;
        #pragma unroll 8
        for (int c = 0; c < CDIM; ++c) {
            float x = zb[(size_t)c * HW + tid];
            s = __fmaf_rn(x, x, s);
        }
        vna[tid] = s;
    }
    __syncthreads();

    // ---- load A fragments ONCE (z static): 8 x ldmatrix.x4 ----
    uint32_t afr[8][4];
    {
        int mat = lane >> 3;
        int ar  = m0 + (lane & 7) + ((mat & 1) << 3);
        uint32_t arow = sb + SM_ZH + ar * 256;
        #pragma unroll
        for (int kk = 0; kk < 8; ++kk) {
            int ac = (kk << 1) + (mat >> 1);
            uint32_t aaddr = arow + (((ac ^ (ar & 7))) << 4);
            asm volatile(
                "ldmatrix.sync.aligned.m8n8.x4.shared.b16 {%0,%1,%2,%3}, [%4];"
                : "=r"(afr[kk][0]), "=r"(afr[kk][1]),
                  "=r"(afr[kk][2]), "=r"(afr[kk][3]) : "r"(aaddr));
        }
    }

    // keyed top-4, rows L (m0+g) and H (m0+g+8)
    uint32_t L1 = 0xFFFFFFFFu, L2 = 0xFFFFFFFFu, L3 = 0xFFFFFFFFu, L4 = 0xFFFFFFFFu;
    uint32_t H1 = 0xFFFFFFFFu, H2 = 0xFFFFFFFFu, H3 = 0xFFFFFFFFu, H4 = 0xFFFFFFFFu;

    // B ldmatrix.x4 lane mapping: lanes 0-15 -> rows of j-pair even member,
    // lanes 16-31 -> odd member; within each, (lane>>3)&1 picks k-chunk parity
    const int b_jhalf = (lane >> 4) & 1;        // 0: first n8 of pair, 1: second
    const int b_kpar  = (lane >> 3) & 1;        // k-chunk parity
    const int b_row   = lane & 7;

    for (int nt = 0; nt < NTILES; ++nt) {
        // ---- stage B tile image (flat 32KB coalesced copy) ----
        {
            const uint4* sh = (const uint4*)g_cbh[nt];
            uint4* dh = (uint4*)(smem + SM_BH);
            #pragma unroll
            for (int i = tid; i < 2048; i += NTHREADS) dh[i] = sh[i];
        }
        __syncthreads();

        #pragma unroll 1
        for (int g32 = 0; g32 < 4; ++g32) {     // 32 codes per group
            float acc[4][4];
            #pragma unroll
            for (int j = 0; j < 4; ++j)
                #pragma unroll
                for (int q = 0; q < 4; ++q) acc[j][q] = 0.f;

            #pragma unroll
            for (int h = 0; h < 2; ++h) {
                // load B frags for 4 kk-steps x 4 j via 8 ldmatrix.x4
                uint32_t bf[4][2][4];           // [kk2][jpair][4 regs]
                #pragma unroll
                for (int kk2 = 0; kk2 < 4; ++kk2) {
                    int bc = ((h << 2) + kk2) * 2 + b_kpar;
                    #pragma unroll
                    for (int jp = 0; jp < 2; ++jp) {
                        int br = (g32 << 5) + (jp << 4) + (b_jhalf << 3) + b_row;
                        uint32_t baddr = sb + SM_BH + br * 256 + (((bc ^ (br & 7))) << 4);
                        asm volatile(
                            "ldmatrix.sync.aligned.m8n8.x4.shared.b16 {%0,%1,%2,%3}, [%4];"
                            : "=r"(bf[kk2][jp][0]), "=r"(bf[kk2][jp][1]),
                              "=r"(bf[kk2][jp][2]), "=r"(bf[kk2][jp][3]) : "r"(baddr));
                    }
                }
                #pragma unroll
                for (int kk2 = 0; kk2 < 4; ++kk2) {
                    int kk = (h << 2) + kk2;
                    #pragma unroll
                    for (int j = 0; j < 4; ++j) {
                        const uint32_t* bp = &bf[kk2][j >> 1][(j & 1) << 1];
                        asm volatile(
                            "mma.sync.aligned.m16n8k16.row.col.f32.bf16.bf16.f32 "
                            "{%0,%1,%2,%3}, {%4,%5,%6,%7}, {%8,%9}, {%0,%1,%2,%3};"
                            : "+f"(acc[j][0]), "+f"(acc[j][1]),
                              "+f"(acc[j][2]), "+f"(acc[j][3])
                            : "r"(afr[kk][0]), "r"(afr[kk][1]),
                              "r"(afr[kk][2]), "r"(afr[kk][3]),
                              "r"(bp[0]), "r"(bp[1]));
                    }
                }
            }

            // ---- keyed approx ranking: r = (se+1) - 2*dot ----
            int kgb = nt * NTL + (g32 << 5);
            #pragma unroll
            for (int j = 0; j < 4; ++j) {
                int c0 = kgb + (j << 3) + (tg << 1);
                float s0 = se1[c0], s1 = se1[c0 + 1];
                ins4(mkkey(__fmaf_rn(-2.f, acc[j][0], s0), c0),     L1, L2, L3, L4);
                ins4(mkkey(__fmaf_rn(-2.f, acc[j][1], s1), c0 + 1), L1, L2, L3, L4);
                ins4(mkkey(__fmaf_rn(-2.f, acc[j][2], s0), c0),     H1, H2, H3, H4);
                ins4(mkkey(__fmaf_rn(-2.f, acc[j][3], s1), c0 + 1), H1, H2, H3, H4);
            }
        }
        __syncthreads();    // all warps done reading BH before restage
    }

    // ---- merge top-4 across the 4 lanes of each quad ----
    #pragma unroll
    for (int d = 1; d <= 2; d <<= 1) {
        uint32_t o1 = __shfl_xor_sync(0xffffffffu, L1, d);
        uint32_t o2 = __shfl_xor_sync(0xffffffffu, L2, d);
        uint32_t o3 = __shfl_xor_sync(0xffffffffu, L3, d);
        uint32_t o4 = __shfl_xor_sync(0xffffffffu, L4, d);
        ins4(o1, L1, L2, L3, L4); ins4(o2, L1, L2, L3, L4);
        ins4(o3, L1, L2, L3, L4); ins4(o4, L1, L2, L3, L4);
        o1 = __shfl_xor_sync(0xffffffffu, H1, d);
        o2 = __shfl_xor_sync(0xffffffffu, H2, d);
        o3 = __shfl_xor_sync(0xffffffffu, H3, d);
        o4 = __shfl_xor_sync(0xffffffffu, H4, d);
        ins4(o1, H1, H2, H3, H4); ins4(o2, H1, H2, H3, H4);
        ins4(o3, H1, H2, H3, H4); ins4(o4, H1, H2, H3, H4);
    }
    if (tg == 0) {
        int rL = m0 + g, rH = m0 + g + 8;
        rk[rL * 4 + 0] = L1 & 1023; rk[rL * 4 + 1] = L2 & 1023;
        rk[rL * 4 + 2] = L3 & 1023; rk[rL * 4 + 3] = L4 & 1023;
        rk[rH * 4 + 0] = H1 & 1023; rk[rH * 4 + 1] = H2 & 1023;
        rk[rH * 4 + 2] = H3 & 1023; rk[rH * 4 + 3] = H4 & 1023;
        float sL1 = __uint_as_float(L1 & 0xFFFFFC00u);
        float sL2 = __uint_as_float(L2 & 0xFFFFFC00u);
        float sH1 = __uint_as_float(H1 & 0xFFFFFC00u);
        float sH2 = __uint_as_float(H2 & 0xFFFFFC00u);
        rne[rL] = (__fsub_rn(sL2, sL1) <= RESCUE_EPS);
        rne[rH] = (__fsub_rn(sH2, sH1) <= RESCUE_EPS);
    }
    __syncthreads();

    // ---- exact 4-way rescue (reference fp32 chain, z from GMEM) + output ----
    float errsum = 0.f;
    if (tid < MV) {
        int v = tid;
        int kb = rk[v * 4];
        if (rne[v]) {
            int k0 = rk[v * 4], k1 = rk[v * 4 + 1],
                k2 = rk[v * 4 + 2], k3 = rk[v * 4 + 3];
            const float* r0 = cb + (size_t)k0 * CDIM;
            const float* r1 = cb + (size_t)k1 * CDIM;
            const float* r2 = cb + (size_t)k2 * CDIM;
            const float* r3 = cb + (size_t)k3 * CDIM;
            float d0 = 0.f, d1 = 0.f, d2 = 0.f, d3 = 0.f;
            #pragma unroll 8
            for (int c = 0; c < CDIM; ++c) {
                float zv = zb[(size_t)c * HW + v];
                d0 = __fmaf_rn(zv, r0[c], d0);
                d1 = __fmaf_rn(zv, r1[c], d1);
                d2 = __fmaf_rn(zv, r2[c], d2);
                d3 = __fmaf_rn(zv, r3[c], d3);
            }
            float vn = vna[v];
            float e0 = __fsub_rn(__fadd_rn(vn, se[k0]), __fmul_rn(2.0f, d0));
            float e1 = __fsub_rn(__fadd_rn(vn, se[k1]), __fmul_rn(2.0f, d1));
            float e2 = __fsub_rn(__fadd_rn(vn, se[k2]), __fmul_rn(2.0f, d2));
            float e3 = __fsub_rn(__fadd_rn(vn, se[k3]), __fmul_rn(2.0f, d3));
            float bd = e0; kb = k0;
            if (e1 < bd || (e1 == bd && k1 < kb)) { bd = e1; kb = k1; }
            if (e2 < bd || (e2 == bd && k2 < kb)) { bd = e2; kb = k2; }
            if (e3 < bd || (e3 == bd && k3 < kb)) { bd = e3; kb = k3; }
        }
        g_used[kb] = 1;

        // z_q_st = fl(z + fl(z_q - z)) in (B,C,H,W); MSE partial
        const float4* crow = (const float4*)(cb + (size_t)kb * CDIM);
        float* ob = out + (size_t)b * CDIM * HW + p0 + v;
        #pragma unroll 4
        for (int c4 = 0; c4 < 32; ++c4) {
            float4 e4 = crow[c4];
            float ee[4] = {e4.x, e4.y, e4.z, e4.w};
            #pragma unroll
            for (int jj = 0; jj < 4; ++jj) {
                int c = c4 * 4 + jj;
                float zv = zb[(size_t)c * HW + v];
                float t  = __fsub_rn(ee[jj], zv);
                ob[(size_t)c * HW] = __fadd_rn(zv, t);
                errsum = __fmaf_rn(t, t, errsum);
            }
        }
    }

    // ---- block reduce squared error -> double atomic ----
    __syncthreads();
    float* red = (float*)(smem + SM_SE);
    if (tid < MV) red[tid] = errsum;
    __syncthreads();
    if (tid < 64) red[tid] = __fadd_rn(red[tid], red[tid + 64]);
    __syncthreads();
    if (tid < 32) {
        float s = __fadd_rn(red[tid], red[tid + 32]);
        #pragma unroll
        for (int off = 16; off; off >>= 1)
            s = __fadd_rn(s, __shfl_down_sync(0xffffffffu, s, off));
        if (tid == 0) atomicAdd(&g_sq, (double)s);
    }
}

// ---------------------------------------------------------------------------
// Kernel 3: finalize — vq_loss + usage scalars
// ---------------------------------------------------------------------------
__global__ void vq_fin(float* __restrict__ out, int npix) {
    __shared__ int cnt[32];
    int tid = threadIdx.x;             // 1024 threads
    int u = g_used[tid] ? 1 : 0;
    #pragma unroll
    for (int off = 16; off; off >>= 1) u += __shfl_down_sync(0xffffffffu, u, off);
    if ((tid & 31) == 0) cnt[tid >> 5] = u;
    __syncthreads();
    if (tid == 0) {
        int total = 0;
        #pragma unroll
        for (int i = 0; i < 32; ++i) total += cnt[i];
        float m  = (float)(g_sq / (double)npix);
        float vq = __fadd_rn(m, __fmul_rn(0.25f, m));
        out[npix]     = vq;
        out[npix + 1] = (float)total * (1.0f / 1024.0f);
    }
}

// ---------------------------------------------------------------------------
extern "C" void kernel_launch(void* const* d_in, const int* in_sizes, int n_in,
                              void* d_out, int out_size) {
    const float* z  = (const float*)d_in[0];
    const float* cb = (const float*)d_in[1];
    float* out = (float*)d_out;
    int npix = out_size - 2;                    // 8388608
    int nvec = npix / CDIM;                     // 65536
    int blocks = nvec / MV;                     // 512

    cudaFuncSetAttribute(vq_mma, cudaFuncAttributeMaxDynamicSharedMemorySize, SM_TOTAL);

    vq_prep<<<KTOT / 4, 128>>>(cb);
    vq_mma<<<blocks, NTHREADS, SM_TOTAL>>>(z, cb, out);
    vq_fin<<<1, KTOT>>>(out, npix);
    vq_nop<<<1, 32>>>();   // shifts ncu -s window toward vq_mma
}